// round 13
// baseline (speedup 1.0000x reference)
#include <cuda_runtime.h>
#include <cuda_pipeline_primitives.h>
#include <cstdint>
#include <cstddef>

// ===========================================================================
// Compile-time CTreeC topology (DEPTH=7, 255 states, 685 edges) with a
// bank-conflict-minimized gather schedule for a 128-thread cooperative scan
// (2 states per thread, 4 warps).
// ===========================================================================
namespace ct {

constexpr int DEPTH  = 7;
constexpr int NS     = (1 << (DEPTH + 1)) - 1;   // 255
constexpr int NE_MAX = 700;                       // actual: 685
constexpr int NT     = 128;                       // threads in scan block
constexpr int NJ     = 2;                         // states per thread

struct Lists { int l[DEPTH + 1]; int r[DEPTH + 1]; int n; int last; };

struct Graph {
  int  ne;
  int  esrc[NE_MAX];
  int  edst[NE_MAX];
  bool is_start[NS];
  bool is_end[NS];
};

constexpr Lists build(int depth, int start, Graph& g) {
  Lists res{};
  if (depth == 0) { res.l[0] = start; res.r[0] = start; res.n = 1; res.last = start; return res; }
  Lists L = build(depth - 1, start, g);
  int my = L.last + 1;
  Lists R = build(depth - 1, my + 1, g);
  for (int i = 0; i < L.n; i++)
    for (int j = 0; j < R.n; j++) { g.esrc[g.ne] = L.r[i]; g.edst[g.ne] = R.l[j]; g.ne++; }
  res.l[0] = my; res.r[0] = my;
  for (int i = 0; i < L.n; i++) { res.l[i + 1] = L.l[i]; res.r[i + 1] = R.r[i]; }
  res.n = L.n + 1; res.last = R.last;
  return res;
}

constexpr Graph make_graph() {
  Graph g{};
  Lists root = build(DEPTH, 0, g);
  for (int i = 0; i <= DEPTH; i++) { g.is_start[root.l[i]] = true; g.is_end[root.r[i]] = true; }
  return g;
}

struct Plan {
  int rowmax[NJ];
  int off[NJ + 1];
  int total;
  int state_of_slot[256];      // -1 for the dummy slot
  int slot_of_state[NS];
  int gidx[16 * NT];           // [(off[j]+k)*NT + tid] = source SLOT (256+tid = pad)
  unsigned start_mask[NT];     // bit j: slot tid*2+j is a start state
  unsigned end_mask[NT];
};

constexpr Plan make_plan() {
  Plan P{};
  Graph g = make_graph();

  int indeg[NS] = {};
  for (int e = 0; e < g.ne; e++) indeg[g.edst[e]]++;

  // insertion sort states by in-degree, descending
  int order[NS] = {};
  for (int i = 0; i < NS; i++) order[i] = i;
  for (int i = 1; i < NS; i++) {
    int x = order[i]; int j = i - 1;
    while (j >= 0 && indeg[order[j]] < indeg[x]) { order[j + 1] = order[j]; j--; }
    order[j + 1] = x;
  }

  // slot s = tid*2 + j; rank r -> tid = r % NT, j = r / NT
  for (int s = 0; s < 256; s++) P.state_of_slot[s] = -1;
  for (int r = 0; r < NS; r++) {
    int tid = r % NT, j = r / NT;
    int slot = tid * NJ + j;
    P.state_of_slot[slot] = order[r];
    P.slot_of_state[order[r]] = slot;
  }

  // per-destination-slot source lists
  int srcs[256][8] = {};
  int cnt[256] = {};
  for (int e = 0; e < g.ne; e++) {
    int ds = P.slot_of_state[g.edst[e]];
    srcs[ds][cnt[ds]++] = P.slot_of_state[g.esrc[e]];
  }

  for (int j = 0; j < NJ; j++) {
    int m = 0;
    for (int tid = 0; tid < NT; tid++)
      if (cnt[tid * NJ + j] > m) m = cnt[tid * NJ + j];
    P.rowmax[j] = m;
  }
  P.off[0] = 0;
  for (int j = 0; j < NJ; j++) P.off[j + 1] = P.off[j] + P.rowmax[j];
  P.total = P.off[NJ];

  for (int i = 0; i < P.total * NT; i++) P.gidx[i] = 256 + (i % NT);  // pads

  // bank-aware greedy column scheduling (conflicts are per-warp)
  bool used[256][8] = {};
  for (int j = 0; j < NJ; j++) {
    for (int k = 0; k < P.rowmax[j]; k++) {
      for (int w = 0; w < NT / 32; w++) {
        int bankcnt[32] = {};
        int chosen[32] = {};
        int nch = 0;
        for (int lane = 0; lane < 32; lane++) {
          int tid = w * 32 + lane;
          int ds = tid * NJ + j;
          int best = -1, bestcost = 1 << 30;
          for (int i = 0; i < cnt[ds]; i++) {
            if (used[ds][i]) continue;
            int s = srcs[ds][i];
            int cost = bankcnt[s & 31];
            for (int q = 0; q < nch; q++) if (chosen[q] == s) { cost = -1; }
            if (cost < bestcost) { bestcost = cost; best = i; }
          }
          if (best >= 0) {
            int s = srcs[ds][best];
            used[ds][best] = true;
            P.gidx[(P.off[j] + k) * NT + tid] = s;
            bool dup = false;
            for (int q = 0; q < nch; q++) if (chosen[q] == s) dup = true;
            if (!dup) { bankcnt[s & 31]++; chosen[nch++] = s; }
          }
        }
      }
    }
  }

  for (int tid = 0; tid < NT; tid++) {
    unsigned sm = 0, em = 0;
    for (int j = 0; j < NJ; j++) {
      int st = P.state_of_slot[tid * NJ + j];
      if (st >= 0) {
        if (g.is_start[st]) sm |= (1u << j);
        if (g.is_end[st])   em |= (1u << j);
      }
    }
    P.start_mask[tid] = sm; P.end_mask[tid] = em;
  }
  return P;
}

constexpr Plan PLAN  = make_plan();
constexpr int  TOTAL = PLAN.total;

}  // namespace ct

__device__ const ct::Plan d_plan = ct::PLAN;

// ===========================================================================
// Fused kernel: one 128-thread block per batch element.
//   - per-thread 4B cp.async gathers lp[state, b, tgt[t]] into smem (each
//     thread fetches exactly the two values it later consumes -> no barriers
//     needed for e-visibility, only __pipeline_wait_prior)
//   - cp.async issue is software-pipelined into the scan loop (chunk q+3
//     issued at quad q; wait_prior(2) keeps chunk q+1 resident)
//   - exp() applied on the prefetched raw value one step before use
// SMEM: es[T*256] raw lp values | tiles (2 x 384 floats) | maxbuf/partials |
//       tgs[T] targets.
// ===========================================================================
template <int OFS, int J>
__device__ __forceinline__ void gather_rows(float (&p)[2],
                                            const unsigned (&ga)[ct::TOTAL]) {
  if constexpr (J < ct::NJ) {
    constexpr int rm = ct::PLAN.rowmax[J];
    constexpr int o  = ct::PLAN.off[J];
    if constexpr (rm == 0) {
      p[J] = 0.0f;
    } else {
      float v[rm];
#pragma unroll
      for (int k = 0; k < rm; k++)
        asm volatile("ld.shared.f32 %0, [%1+%2];" : "=f"(v[k]) : "r"(ga[o + k]), "n"(OFS));
#pragma unroll
      for (int s2 = 1; s2 < rm; s2 *= 2)
#pragma unroll
        for (int k = 0; k + s2 < rm; k += 2 * s2) v[k] += v[k + s2];
      p[J] = v[0];
    }
    gather_rows<OFS, J + 1>(p, ga);
  }
}

// ex holds exp'd e-values for the CURRENT step; raw prefetch + exp for the
// next step happens before the barrier (off the critical path). Raw values
// are clamped to <= 0 (log-softmax domain) so even a never-consumed garbage
// prefetch stays finite.
template <int OFS, bool DOMAX, bool LOADMAX>
__device__ __forceinline__ void step_body(float (&p)[2], float2& ex,
                                          const float2*& ep,
                                          const unsigned (&ga)[ct::TOTAL],
                                          unsigned wa, float& lm, float4& mxv,
                                          unsigned mba, float eymul) {
  float c0 = p[0] * ex.x, c1 = p[1] * ex.y;
  asm volatile("st.shared.v2.f32 [%0+%1], {%2,%3};"
      :: "r"(wa), "n"(OFS), "f"(c0), "f"(c1) : "memory");
  if constexpr (DOMAX) lm = fmaxf(c0, c1);
  float2 raw = *ep; ep += ct::NT;
  ex.x = __expf(fminf(raw.x, 0.0f));
  ex.y = __expf(fminf(raw.y, 0.0f)) * eymul;
  __syncthreads();
  if constexpr (LOADMAX)          // maxbuf written 2 steps ago, now visible
    asm volatile("ld.shared.v4.f32 {%0,%1,%2,%3}, [%4];"
        : "=f"(mxv.x), "=f"(mxv.y), "=f"(mxv.z), "=f"(mxv.w) : "r"(mba));
  gather_rows<OFS, 0>(p, ga);
}

__device__ __forceinline__ void issue_chunk(int k, int len,
                                            const float* __restrict__ base0,
                                            const float* __restrict__ base1,
                                            float* dst, const int* tgs) {
  int t0 = k * 4;
  int t1 = t0 + 4 < len ? t0 + 4 : len;
#pragma unroll 4
  for (int t = t0; t < t1; t++) {
    int tg = tgs[t];
    __pipeline_memcpy_async(dst + t * 256,     base0 + tg, 4);
    __pipeline_memcpy_async(dst + t * 256 + 1, base1 + tg, 4);
  }
  __pipeline_commit();   // empty group (t0 >= len) completes immediately
}

__device__ __forceinline__ void run_quad(float (&p)[2], float2& ex,
                                         const float2*& ep,
                                         const unsigned (&ga)[ct::TOTAL],
                                         unsigned wa, unsigned mba,
                                         int lane, int warp, int& eacc,
                                         float eymul) {
  float lm = 0.0f;
  float4 mxv;
  step_body<0,    false, false>(p, ex, ep, ga, wa, lm, mxv, mba, eymul);
  step_body<1536, true,  false>(p, ex, ep, ga, wa, lm, mxv, mba, eymul);
  // per-warp max of this quad's c -> smem; visible after next step's barrier
  unsigned mr = __reduce_max_sync(0xffffffffu, __float_as_uint(lm));
  if (lane == 0)
    asm volatile("st.shared.u32 [%0], %1;" :: "r"(mba + (unsigned)warp * 4u), "r"(mr) : "memory");
  step_body<0,    false, true >(p, ex, ep, ga, wa, lm, mxv, mba, eymul);
  // combine 4 warp maxima; exponent-only rescale (exact power of two)
  float mx = fmaxf(fmaxf(mxv.x, mxv.y), fmaxf(mxv.z, mxv.w));
  int e = (int)(__float_as_uint(mx) >> 23) - 127;
  eacc += e;
  float scale = __uint_as_float((unsigned)(127 - e) << 23);
  p[0] *= scale; p[1] *= scale;
  step_body<1536, false, false>(p, ex, ep, ga, wa, lm, mxv, mba, eymul);
}

__global__ void __launch_bounds__(ct::NT, 1)
scan_kernel(const float* __restrict__ lp, const int* __restrict__ tgt,
            const int* __restrict__ lens, float* __restrict__ out,
            int B, int T, int vocab) {
  extern __shared__ float dyn[];
  int b   = blockIdx.x;
  int tid = threadIdx.x;
  int lane = tid & 31, warp = tid >> 5;

  int len = lens[b];
  if (len < 1) len = 1;
  if (len > T) len = T;

  float* es  = dyn;                       // T*256 raw lp values
  float* scp = dyn + (size_t)T * 256;     // tiles + maxbuf
  int*   tgs = (int*)(scp + 772);         // T targets

  // load this batch element's targets
  for (int t = tid; t < len; t += ct::NT) tgs[t] = tgt[t * B + b];
  __syncthreads();

  // per-thread source rows in lp (2 owned states)
  int st0 = d_plan.state_of_slot[2 * tid];
  int st1 = d_plan.state_of_slot[2 * tid + 1];
  float eymul = (st1 < 0) ? 0.0f : 1.0f;        // dummy slot (thread 127)
  if (st1 < 0) st1 = 0;                         // safe, finite source row
  const float* base0 = lp + ((size_t)st0 * B + b) * (size_t)vocab;
  const float* base1 = lp + ((size_t)st1 * B + b) * (size_t)vocab;
  float* dst = es + 2 * tid;

  // prime the pipeline with chunks 0, 1, 2 (12 steps of slack)
  issue_chunk(0, len, base0, base1, dst, tgs);
  issue_chunk(1, len, base0, base1, dst, tgs);
  issue_chunk(2, len, base0, base1, dst, tgs);

  // setup overlapped with the copies in flight
  unsigned sc0a = (unsigned)__cvta_generic_to_shared(scp);
  unsigned mba  = sc0a + 3072u;
  unsigned ga[ct::TOTAL];
#pragma unroll
  for (int q = 0; q < ct::TOTAL; q++)
    ga[q] = sc0a + (unsigned)d_plan.gidx[q * ct::NT + tid] * 4u;
  unsigned wa = sc0a + (unsigned)tid * 8u;
  scp[256 + tid]       = 0.0f;    // per-thread zero pad, tile 0 (self-read)
  scp[384 + 256 + tid] = 0.0f;    // per-thread zero pad, tile 1 (self-read)
  unsigned smask = d_plan.start_mask[tid];
  unsigned emask = d_plan.end_mask[tid];

  float p[2];
  p[0] = (smask & 1u) ? 1.0f : 0.0f;
  p[1] = (smask & 2u) ? 1.0f : 0.0f;

  // chunk 0 landed (this thread's own data; no barrier needed)
  __pipeline_wait_prior(2);
  const float2* ep = (const float2*)es + tid;
  float2 raw0 = *ep;
  ep += ct::NT;
  float2 ex;
  ex.x = __expf(fminf(raw0.x, 0.0f));
  ex.y = __expf(fminf(raw0.y, 0.0f)) * eymul;

  int nfull = (len - 1) >> 2;
  int rem   = (len - 1) & 3;

  int eacc = 0;
  float lmd; float4 mxd;

  for (int q = 0; q < nfull; q++) {
    issue_chunk(q + 3, len, base0, base1, dst, tgs);  // hidden in issue slots
    __pipeline_wait_prior(2);                          // chunks <= q+1 resident
    run_quad(p, ex, ep, ga, wa, mba, lane, warp, eacc, eymul);
  }

  __pipeline_wait_prior(0);   // everything resident for the tail
  if (rem >= 1) step_body<0,    false, false>(p, ex, ep, ga, wa, lmd, mxd, mba, eymul);
  if (rem >= 2) step_body<1536, false, false>(p, ex, ep, ga, wa, lmd, mxd, mba, eymul);
  if (rem >= 3) step_body<0,    false, false>(p, ex, ep, ga, wa, lmd, mxd, mba, eymul);

  // final step (t = len-1): no scatter; reduce over END states
  float c0 = p[0] * ex.x, c1 = p[1] * ex.y;
  float s = ((emask & 1u) ? c0 : 0.0f) + ((emask & 2u) ? c1 : 0.0f);
#pragma unroll
  for (int o = 16; o > 0; o >>= 1) s += __shfl_xor_sync(0xffffffffu, s, o);
  __syncthreads();
  if (lane == 0) scp[768 + warp] = s;
  __syncthreads();
  if (tid == 0) {
    float tot = scp[768] + scp[769] + scp[770] + scp[771];
    out[b] = -((float)eacc * 0.69314718055994531f + logf(tot));
  }
}

// ===========================================================================
extern "C" void kernel_launch(void* const* d_in, const int* in_sizes, int n_in,
                              void* d_out, int out_size) {
  const float* lp   = (const float*)d_in[0];   // log_probs (V,B,vocab) f32
  const int*   tgt  = (const int*)d_in[1];     // targets (T,B) i32
  const int*   lens = (const int*)d_in[2];     // target_lengths (B,) i32
  float* out = (float*)d_out;

  int B = in_sizes[2];
  int T = in_sizes[1] / B;
  int vocab = in_sizes[0] / (ct::NS * B);

  size_t shbytes = ((size_t)T * 256 + 772 + T + 4) * sizeof(float);
  cudaFuncSetAttribute(scan_kernel, cudaFuncAttributeMaxDynamicSharedMemorySize,
                       (int)shbytes);
  scan_kernel<<<B, ct::NT, shbytes>>>(lp, tgt, lens, out, B, T, vocab);
}

// round 14
// speedup vs baseline: 1.2166x; 1.2166x over previous
#include <cuda_runtime.h>
#include <cstdint>
#include <cstddef>

// ===========================================================================
// Compile-time CTreeC topology (DEPTH=7, 255 states, 685 edges) with a
// bank-conflict-minimized gather schedule for a 128-thread cooperative scan
// (2 states per thread, 4 warps).
// ===========================================================================
namespace ct {

constexpr int DEPTH  = 7;
constexpr int NS     = (1 << (DEPTH + 1)) - 1;   // 255
constexpr int NE_MAX = 700;                       // actual: 685
constexpr int NT     = 128;                       // threads in scan block
constexpr int NJ     = 2;                         // states per thread

struct Lists { int l[DEPTH + 1]; int r[DEPTH + 1]; int n; int last; };

struct Graph {
  int  ne;
  int  esrc[NE_MAX];
  int  edst[NE_MAX];
  bool is_start[NS];
  bool is_end[NS];
};

constexpr Lists build(int depth, int start, Graph& g) {
  Lists res{};
  if (depth == 0) { res.l[0] = start; res.r[0] = start; res.n = 1; res.last = start; return res; }
  Lists L = build(depth - 1, start, g);
  int my = L.last + 1;
  Lists R = build(depth - 1, my + 1, g);
  for (int i = 0; i < L.n; i++)
    for (int j = 0; j < R.n; j++) { g.esrc[g.ne] = L.r[i]; g.edst[g.ne] = R.l[j]; g.ne++; }
  res.l[0] = my; res.r[0] = my;
  for (int i = 0; i < L.n; i++) { res.l[i + 1] = L.l[i]; res.r[i + 1] = R.r[i]; }
  res.n = L.n + 1; res.last = R.last;
  return res;
}

constexpr Graph make_graph() {
  Graph g{};
  Lists root = build(DEPTH, 0, g);
  for (int i = 0; i <= DEPTH; i++) { g.is_start[root.l[i]] = true; g.is_end[root.r[i]] = true; }
  return g;
}

struct Plan {
  int rowmax[NJ];
  int off[NJ + 1];
  int total;
  int state_of_slot[256];      // -1 for the dummy slot
  int slot_of_state[NS];
  int gidx[16 * NT];           // [(off[j]+k)*NT + tid] = source SLOT (256+tid = pad)
  unsigned start_mask[NT];     // bit j: slot tid*2+j is a start state
  unsigned end_mask[NT];
};

constexpr Plan make_plan() {
  Plan P{};
  Graph g = make_graph();

  int indeg[NS] = {};
  for (int e = 0; e < g.ne; e++) indeg[g.edst[e]]++;

  // insertion sort states by in-degree, descending
  int order[NS] = {};
  for (int i = 0; i < NS; i++) order[i] = i;
  for (int i = 1; i < NS; i++) {
    int x = order[i]; int j = i - 1;
    while (j >= 0 && indeg[order[j]] < indeg[x]) { order[j + 1] = order[j]; j--; }
    order[j + 1] = x;
  }

  // slot s = tid*2 + j; rank r -> tid = r % NT, j = r / NT
  for (int s = 0; s < 256; s++) P.state_of_slot[s] = -1;
  for (int r = 0; r < NS; r++) {
    int tid = r % NT, j = r / NT;
    int slot = tid * NJ + j;
    P.state_of_slot[slot] = order[r];
    P.slot_of_state[order[r]] = slot;
  }

  // per-destination-slot source lists
  int srcs[256][8] = {};
  int cnt[256] = {};
  for (int e = 0; e < g.ne; e++) {
    int ds = P.slot_of_state[g.edst[e]];
    srcs[ds][cnt[ds]++] = P.slot_of_state[g.esrc[e]];
  }

  for (int j = 0; j < NJ; j++) {
    int m = 0;
    for (int tid = 0; tid < NT; tid++)
      if (cnt[tid * NJ + j] > m) m = cnt[tid * NJ + j];
    P.rowmax[j] = m;
  }
  P.off[0] = 0;
  for (int j = 0; j < NJ; j++) P.off[j + 1] = P.off[j] + P.rowmax[j];
  P.total = P.off[NJ];

  for (int i = 0; i < P.total * NT; i++) P.gidx[i] = 256 + (i % NT);  // pads

  // bank-aware greedy column scheduling (conflicts are per-warp)
  bool used[256][8] = {};
  for (int j = 0; j < NJ; j++) {
    for (int k = 0; k < P.rowmax[j]; k++) {
      for (int w = 0; w < NT / 32; w++) {
        int bankcnt[32] = {};
        int chosen[32] = {};
        int nch = 0;
        for (int lane = 0; lane < 32; lane++) {
          int tid = w * 32 + lane;
          int ds = tid * NJ + j;
          int best = -1, bestcost = 1 << 30;
          for (int i = 0; i < cnt[ds]; i++) {
            if (used[ds][i]) continue;
            int s = srcs[ds][i];
            int cost = bankcnt[s & 31];
            for (int q = 0; q < nch; q++) if (chosen[q] == s) { cost = -1; }
            if (cost < bestcost) { bestcost = cost; best = i; }
          }
          if (best >= 0) {
            int s = srcs[ds][best];
            used[ds][best] = true;
            P.gidx[(P.off[j] + k) * NT + tid] = s;
            bool dup = false;
            for (int q = 0; q < nch; q++) if (chosen[q] == s) dup = true;
            if (!dup) { bankcnt[s & 31]++; chosen[nch++] = s; }
          }
        }
      }
    }
  }

  for (int tid = 0; tid < NT; tid++) {
    unsigned sm = 0, em = 0;
    for (int j = 0; j < NJ; j++) {
      int st = P.state_of_slot[tid * NJ + j];
      if (st >= 0) {
        if (g.is_start[st]) sm |= (1u << j);
        if (g.is_end[st])   em |= (1u << j);
      }
    }
    P.start_mask[tid] = sm; P.end_mask[tid] = em;
  }
  return P;
}

constexpr Plan PLAN  = make_plan();
constexpr int  TOTAL = PLAN.total;

}  // namespace ct

__device__ const ct::Plan d_plan = ct::PLAN;

// ===========================================================================
// Single fused kernel: one 128-thread block per batch element.
//   - per-step, each thread issues 2 LDG.32 directly from log_probs into a
//     4-deep register ring (prefetch distance 4 steps ~ covers DRAM latency;
//     loads are spread in time -> no per-SM L1tex pileup)
//   - exp() applied on the prefetched raw value one step before use
//   - 2 states/thread cooperative scan, one __syncthreads per step,
//     block-wide exponent-only renorm every 4 steps (all as in R10)
// SMEM: tiles (2 x 384 floats) | maxbuf/partials | tgs[T] targets. ~3.5 KB.
// ===========================================================================
template <int OFS, int J>
__device__ __forceinline__ void gather_rows(float (&p)[2],
                                            const unsigned (&ga)[ct::TOTAL]) {
  if constexpr (J < ct::NJ) {
    constexpr int rm = ct::PLAN.rowmax[J];
    constexpr int o  = ct::PLAN.off[J];
    if constexpr (rm == 0) {
      p[J] = 0.0f;
    } else {
      float v[rm];
#pragma unroll
      for (int k = 0; k < rm; k++)
        asm volatile("ld.shared.f32 %0, [%1+%2];" : "=f"(v[k]) : "r"(ga[o + k]), "n"(OFS));
#pragma unroll
      for (int s2 = 1; s2 < rm; s2 *= 2)
#pragma unroll
        for (int k = 0; k + s2 < rm; k += 2 * s2) v[k] += v[k + s2];
      p[J] = v[0];
    }
    gather_rows<OFS, J + 1>(p, ga);
  }
}

// Step t: consume ex (= exp'd e for step t); issue LDG prefetch for step t+4
// into ring slot SLOT (= t % 4); convert ring slot (t+1)%4 -> ex for the next
// step. Raw values clamped to <= 0 (log-softmax domain) so even unconsumed
// tail prefetches stay finite.
template <int OFS, int SLOT, bool DOMAX, bool LOADMAX>
__device__ __forceinline__ void step_body(float (&p)[2], float2& ex,
                                          float2 (&rr)[4], int tp,
                                          const int* __restrict__ tgs,
                                          const float* __restrict__ base0,
                                          const float* __restrict__ base1,
                                          const unsigned (&ga)[ct::TOTAL],
                                          unsigned wa, float& lm, float4& mxv,
                                          unsigned mba, float eymul) {
  float c0 = p[0] * ex.x, c1 = p[1] * ex.y;
  asm volatile("st.shared.v2.f32 [%0+%1], {%2,%3};"
      :: "r"(wa), "n"(OFS), "f"(c0), "f"(c1) : "memory");
  if constexpr (DOMAX) lm = fmaxf(c0, c1);
  // issue prefetch for step t+4 (slot t%4; old value consumed at step t-1)
  {
    int tg = tgs[tp];
    rr[SLOT].x = base0[tg];
    rr[SLOT].y = base1[tg];
  }
  // convert next step's raw (loaded 3 steps ago) -> exp'd
  {
    float2 rn = rr[(SLOT + 1) & 3];
    ex.x = __expf(fminf(rn.x, 0.0f));
    ex.y = __expf(fminf(rn.y, 0.0f)) * eymul;
  }
  __syncthreads();
  if constexpr (LOADMAX)          // maxbuf written 2 steps ago, now visible
    asm volatile("ld.shared.v4.f32 {%0,%1,%2,%3}, [%4];"
        : "=f"(mxv.x), "=f"(mxv.y), "=f"(mxv.z), "=f"(mxv.w) : "r"(mba));
  gather_rows<OFS, 0>(p, ga);
}

__device__ __forceinline__ void run_quad(float (&p)[2], float2& ex,
                                         float2 (&rr)[4], int t0, int lenm1,
                                         const int* __restrict__ tgs,
                                         const float* __restrict__ base0,
                                         const float* __restrict__ base1,
                                         const unsigned (&ga)[ct::TOTAL],
                                         unsigned wa, unsigned mba,
                                         int lane, int warp, int& eacc,
                                         float eymul) {
  float lm = 0.0f;
  float4 mxv;
  step_body<0,    0, false, false>(p, ex, rr, min(t0 + 4, lenm1), tgs, base0, base1, ga, wa, lm, mxv, mba, eymul);
  step_body<1536, 1, true,  false>(p, ex, rr, min(t0 + 5, lenm1), tgs, base0, base1, ga, wa, lm, mxv, mba, eymul);
  // per-warp max of this quad's c -> smem; visible after next step's barrier
  unsigned mr = __reduce_max_sync(0xffffffffu, __float_as_uint(lm));
  if (lane == 0)
    asm volatile("st.shared.u32 [%0], %1;" :: "r"(mba + (unsigned)warp * 4u), "r"(mr) : "memory");
  step_body<0,    2, false, true >(p, ex, rr, min(t0 + 6, lenm1), tgs, base0, base1, ga, wa, lm, mxv, mba, eymul);
  // combine 4 warp maxima; exponent-only rescale (exact power of two)
  float mx = fmaxf(fmaxf(mxv.x, mxv.y), fmaxf(mxv.z, mxv.w));
  int e = (int)(__float_as_uint(mx) >> 23) - 127;
  eacc += e;
  float scale = __uint_as_float((unsigned)(127 - e) << 23);
  p[0] *= scale; p[1] *= scale;
  step_body<1536, 3, false, false>(p, ex, rr, min(t0 + 7, lenm1), tgs, base0, base1, ga, wa, lm, mxv, mba, eymul);
}

__global__ void __launch_bounds__(ct::NT, 1)
scan_kernel(const float* __restrict__ lp, const int* __restrict__ tgt,
            const int* __restrict__ lens, float* __restrict__ out,
            int B, int T, int vocab) {
  extern __shared__ float dyn[];
  int b   = blockIdx.x;
  int tid = threadIdx.x;
  int lane = tid & 31, warp = tid >> 5;

  int len = lens[b];
  if (len < 1) len = 1;
  if (len > T) len = T;
  int lenm1 = len - 1;

  float* scp = dyn;                 // tiles (2x384) + maxbuf/partials (772)
  int*   tgs = (int*)(dyn + 772);   // T targets

  // load this batch element's targets; zero pads before the same barrier
  for (int t = tid; t < len; t += ct::NT) tgs[t] = tgt[t * B + b];
  scp[256 + tid]       = 0.0f;      // per-thread zero pad, tile 0 (self-read)
  scp[384 + 256 + tid] = 0.0f;      // per-thread zero pad, tile 1 (self-read)
  __syncthreads();

  // per-thread source rows in lp (2 owned states)
  int st0 = d_plan.state_of_slot[2 * tid];
  int st1 = d_plan.state_of_slot[2 * tid + 1];
  float eymul = (st1 < 0) ? 0.0f : 1.0f;        // dummy slot (thread 127)
  if (st1 < 0) st1 = 0;                         // safe, finite source row
  const float* base0 = lp + ((size_t)st0 * B + b) * (size_t)vocab;
  const float* base1 = lp + ((size_t)st1 * B + b) * (size_t)vocab;

  unsigned sc0a = (unsigned)__cvta_generic_to_shared(scp);
  unsigned mba  = sc0a + 3072u;
  unsigned ga[ct::TOTAL];
#pragma unroll
  for (int q = 0; q < ct::TOTAL; q++)
    ga[q] = sc0a + (unsigned)d_plan.gidx[q * ct::NT + tid] * 4u;
  unsigned wa = sc0a + (unsigned)tid * 8u;
  unsigned smask = d_plan.start_mask[tid];
  unsigned emask = d_plan.end_mask[tid];

  float p[2];
  p[0] = (smask & 1u) ? 1.0f : 0.0f;
  p[1] = (smask & 2u) ? 1.0f : 0.0f;

  // prime the register ring with raw values for steps 0..3 (clamped)
  float2 rr[4];
#pragma unroll
  for (int k = 0; k < 4; k++) {
    int tg = tgs[min(k, lenm1)];
    rr[k].x = base0[tg];
    rr[k].y = base1[tg];
  }
  float2 ex;
  ex.x = __expf(fminf(rr[0].x, 0.0f));
  ex.y = __expf(fminf(rr[0].y, 0.0f)) * eymul;

  int nfull = (len - 1) >> 2;
  int rem   = (len - 1) & 3;

  int eacc = 0;
  float lmd; float4 mxd;

  for (int q = 0; q < nfull; q++)
    run_quad(p, ex, rr, 4 * q, lenm1, tgs, base0, base1, ga, wa, mba,
             lane, warp, eacc, eymul);

  // tail steps (slots continue the t%4 pattern: 0,1,2)
  if (rem >= 1) step_body<0,    0, false, false>(p, ex, rr, lenm1, tgs, base0, base1, ga, wa, lmd, mxd, mba, eymul);
  if (rem >= 2) step_body<1536, 1, false, false>(p, ex, rr, lenm1, tgs, base0, base1, ga, wa, lmd, mxd, mba, eymul);
  if (rem >= 3) step_body<0,    2, false, false>(p, ex, rr, lenm1, tgs, base0, base1, ga, wa, lmd, mxd, mba, eymul);

  // final step (t = len-1): no scatter; reduce over END states
  float c0 = p[0] * ex.x, c1 = p[1] * ex.y;
  float s = ((emask & 1u) ? c0 : 0.0f) + ((emask & 2u) ? c1 : 0.0f);
#pragma unroll
  for (int o = 16; o > 0; o >>= 1) s += __shfl_xor_sync(0xffffffffu, s, o);
  __syncthreads();
  if (lane == 0) scp[768 + warp] = s;
  __syncthreads();
  if (tid == 0) {
    float tot = scp[768] + scp[769] + scp[770] + scp[771];
    out[b] = -((float)eacc * 0.69314718055994531f + logf(tot));
  }
}

// ===========================================================================
extern "C" void kernel_launch(void* const* d_in, const int* in_sizes, int n_in,
                              void* d_out, int out_size) {
  const float* lp   = (const float*)d_in[0];   // log_probs (V,B,vocab) f32
  const int*   tgt  = (const int*)d_in[1];     // targets (T,B) i32
  const int*   lens = (const int*)d_in[2];     // target_lengths (B,) i32
  float* out = (float*)d_out;

  int B = in_sizes[2];
  int T = in_sizes[1] / B;
  int vocab = in_sizes[0] / (ct::NS * B);

  size_t shbytes = (772 + (size_t)T) * sizeof(float);
  scan_kernel<<<B, ct::NT, shbytes>>>(lp, tgt, lens, out, B, T, vocab);
}